// round 16
// baseline (speedup 1.0000x reference)
#include <cuda_runtime.h>
#include <cuda_bf16.h>
#include <math.h>
#include <stdint.h>

#define BB   256
#define KK   64
#define DD   2048
#define NPTS 50000
#define CC   5000
#define NHID 512
#define HH2  256
#define MM   (BB*KK)        // 16384
#define MU   5376           // padded unique rows: 5000 clusters + 256 pivots + pad

// ---------------- scratch (device globals; no allocations allowed) ----------
__device__ int   g_icnt[CC];
__device__ int   g_off[CC];
__device__ int   g_wptr[CC];
__device__ int   g_sidx[NPTS];
__device__ __nv_bfloat16 g_Mh[(size_t)MU*DD];    // UNnormalized rows hi/lo (gram)
__device__ __nv_bfloat16 g_Ml[(size_t)MU*DD];
__device__ __nv_bfloat16 g_A1h[(size_t)MU*DD];   // normalized rows (layer1 input)
__device__ __nv_bfloat16 g_W1h[(size_t)1024*DD]; // W1^T fused [1024 x 2048]
__device__ __nv_bfloat16 g_W2h[(size_t)512*NHID];
__device__ __nv_bfloat16 g_Wch[(size_t)HH2*HH2];
__device__ float g_U [(size_t)MU*1024];          // layer1 unique-row outputs [top|bot]
__device__ __nv_bfloat16 g_X1h[(size_t)MM*NHID];
__device__ float g_Z [(size_t)MM*NHID];          // layer2 outputs [top|bot] per row
__device__ __nv_bfloat16 g_X2h[(size_t)MM*HH2];
__device__ float g_part[2][(size_t)MM*2];        // fused-head partials per col-block
__device__ float g_G  [(size_t)BB*KK*KK];
__device__ float g_Adj[(size_t)BB*KK*KK];
__device__ int   g_row[MM];

// ---------------- streams/events for graph-level parallelism -----------------
static cudaStream_t g_s1, g_s2;
static cudaEvent_t  g_evF1, g_evF2, g_evW, g_evG, g_evZ, g_evR;
static int g_async_init = [](){
    cudaStreamCreateWithFlags(&g_s1, cudaStreamNonBlocking);
    cudaStreamCreateWithFlags(&g_s2, cudaStreamNonBlocking);
    cudaEventCreateWithFlags(&g_evF1, cudaEventDisableTiming);
    cudaEventCreateWithFlags(&g_evF2, cudaEventDisableTiming);
    cudaEventCreateWithFlags(&g_evW,  cudaEventDisableTiming);
    cudaEventCreateWithFlags(&g_evG,  cudaEventDisableTiming);
    cudaEventCreateWithFlags(&g_evZ,  cudaEventDisableTiming);
    cudaEventCreateWithFlags(&g_evR,  cudaEventDisableTiming);
    return 0;
}();

// ---------------- helpers -----------------------------------------------------

__device__ __forceinline__ uint32_t smem_u32(const void* p) {
    uint32_t a;
    asm("{ .reg .u64 t; cvta.to.shared.u64 t, %1; cvt.u32.u64 %0, t; }"
        : "=r"(a) : "l"(p));
    return a;
}

#define CP_ASYNC16(saddr, gaddr) \
    asm volatile("cp.async.cg.shared.global [%0], [%1], 16;\n" \
                 :: "r"(saddr), "l"(gaddr))
#define CP_COMMIT() asm volatile("cp.async.commit_group;\n" ::: "memory")
#define CP_WAIT0()  asm volatile("cp.async.wait_group 0;\n" ::: "memory")
#define CP_WAIT1()  asm volatile("cp.async.wait_group 1;\n" ::: "memory")

#define LDMATRIX_X4(d0,d1,d2,d3, addr) \
    asm volatile("ldmatrix.sync.aligned.m8n8.x4.shared.b16 {%0,%1,%2,%3}, [%4];\n" \
        : "=r"(d0), "=r"(d1), "=r"(d2), "=r"(d3) : "r"(addr))

#define MMA16816(c, a, b0v, b1v) \
    asm volatile("mma.sync.aligned.m16n8k16.row.col.f32.bf16.bf16.f32 " \
        "{%0,%1,%2,%3}, {%4,%5,%6,%7}, {%8,%9}, {%0,%1,%2,%3};\n" \
        : "+f"((c)[0]), "+f"((c)[1]), "+f"((c)[2]), "+f"((c)[3]) \
        : "r"((a)[0]), "r"((a)[1]), "r"((a)[2]), "r"((a)[3]), \
          "r"(b0v), "r"(b1v))

// ---------------- cluster-mean pipeline (sorted, no big atomics) --------------

__global__ void k_zeroc()
{
    int i = blockIdx.x*blockDim.x + threadIdx.x;
    if (i < CC) g_icnt[i] = 0;
}

// int4-vectorized histogram (NPTS divisible by 4)
__global__ void k_count(const int* __restrict__ labels)
{
    int i = blockIdx.x*blockDim.x + threadIdx.x;
    if (i < NPTS/4) {
        int4 l = ((const int4*)labels)[i];
        atomicAdd(&g_icnt[l.x], 1);
        atomicAdd(&g_icnt[l.y], 1);
        atomicAdd(&g_icnt[l.z], 1);
        atomicAdd(&g_icnt[l.w], 1);
    }
}

// exclusive prefix over CC counts, single block of 256
__global__ void k_scan()
{
    __shared__ int wsum[8];
    int t = threadIdx.x, lane = t & 31, w = t >> 5;
    int local[20];
    int s = 0;
    #pragma unroll
    for (int j = 0; j < 20; j++) {
        int c = t*20 + j;
        int v = (c < CC) ? g_icnt[c] : 0;
        local[j] = s;
        s += v;
    }
    int x = s;
    #pragma unroll
    for (int o = 1; o < 32; o <<= 1) {
        int y = __shfl_up_sync(0xFFFFFFFFu, x, o);
        if (lane >= o) x += y;
    }
    if (lane == 31) wsum[w] = x;
    __syncthreads();
    if (t == 0) {
        int acc = 0;
        #pragma unroll
        for (int i = 0; i < 8; i++) { int v = wsum[i]; wsum[i] = acc; acc += v; }
    }
    __syncthreads();
    int base = wsum[w] + (x - s);
    #pragma unroll
    for (int j = 0; j < 20; j++) {
        int c = t*20 + j;
        if (c < CC) { g_off[c] = base + local[j]; g_wptr[c] = base + local[j]; }
    }
}

// int4-vectorized scatter (NPTS divisible by 4)
__global__ void k_scatter(const int* __restrict__ labels)
{
    int i = blockIdx.x*blockDim.x + threadIdx.x;
    if (i < NPTS/4) {
        int4 l = ((const int4*)labels)[i];
        int base = i*4;
        g_sidx[atomicAdd(&g_wptr[l.x], 1)] = base;
        g_sidx[atomicAdd(&g_wptr[l.y], 1)] = base + 1;
        g_sidx[atomicAdd(&g_wptr[l.z], 1)] = base + 2;
        g_sidx[atomicAdd(&g_wptr[l.w], 1)] = base + 3;
    }
}

// rows [0,CC): cluster mean; rows [CC,CC+BB): pivot features.
__global__ __launch_bounds__(256)
void k_cmean(const float* __restrict__ feats,
             const int* __restrict__ indexes,
             float* __restrict__ simm_out)
{
    __shared__ float red[256];
    int c = blockIdx.x, t = threadIdx.x;
    float4 s0 = {0,0,0,0}, s1 = {0,0,0,0};
    float invn;
    if (c < CC) {
        int n = g_icnt[c], base = g_off[c];
        for (int r = 0; r < n; r++) {
            const float4* f = (const float4*)(feats + (size_t)g_sidx[base + r]*DD);
            float4 a = f[t], b = f[t + 256];
            s0.x += a.x; s0.y += a.y; s0.z += a.z; s0.w += a.w;
            s1.x += b.x; s1.y += b.y; s1.z += b.z; s1.w += b.w;
        }
        invn = 1.0f / (float)max(n, 1);
    } else {
        const float4* f = (const float4*)(feats + (size_t)indexes[c - CC]*DD);
        s0 = f[t]; s1 = f[t + 256];
        invn = 1.0f;
    }
    float m[8] = { s0.x*invn, s0.y*invn, s0.z*invn, s0.w*invn,
                   s1.x*invn, s1.y*invn, s1.z*invn, s1.w*invn };
    float ss = 0.f;
    #pragma unroll
    for (int j = 0; j < 8; j++) ss += m[j]*m[j];
    red[t] = ss;
    __syncthreads();
    for (int o = 128; o > 0; o >>= 1) {
        if (t < o) red[t] += red[t + o];
        __syncthreads();
    }
    float s = red[0];
    if (c < CC && t == 0) simm_out[c] = s;
    float inv = (s > 0.f) ? rsqrtf(s) : 0.f;
    size_t rb = (size_t)c*DD;
    #pragma unroll
    for (int j = 0; j < 8; j++) {
        int d = (j < 4) ? (t*4 + j) : (1024 + t*4 + (j - 4));
        float v = m[j];
        __nv_bfloat16 h = __float2bfloat16(v);
        g_Mh[rb + d] = h;
        g_Ml[rb + d] = __float2bfloat16(v - __bfloat162float(h));
        g_A1h[rb + d] = __float2bfloat16(v*inv);
    }
}

__global__ void k_rowmap(const int* __restrict__ labels,
                         const int* __restrict__ knn)
{
    int i = blockIdx.x*blockDim.x + threadIdx.x;
    if (i >= MM) return;
    int b = i / KK, k = i % KK;
    g_row[i] = (k == 0) ? (CC + b) : labels[knn[i]];
}

// weight transpose + bf16 (hi only)
__global__ void k_convW(const float* __restrict__ W, int ldw, int Kd, int Nh,
                        __nv_bfloat16* __restrict__ dh)
{
    size_t i = (size_t)blockIdx.x*blockDim.x + threadIdx.x;
    int n = (int)(i / Kd), k = (int)(i % Kd);
    int col  = (n < Nh) ? n : n - Nh;
    int koff = (n < Nh) ? 0 : Kd;
    dh[i] = __float2bfloat16(W[(size_t)(koff + k)*ldw + col]);
}

// ---------------- gram via mma (bf16x3, gathered rows) ------------------------

#define GTS 72   // smem row stride (elems)

__global__ __launch_bounds__(256)
void k_gram_mma()
{
    __shared__ int rows[KK];
    __shared__ __align__(16) __nv_bfloat16 buf[2][2][KK*GTS];
    int b = blockIdx.x, t = threadIdx.x;
    int lane = t & 31, wid = t >> 5;
    int wr = wid & 3, wc = wid >> 2;

    if (t < KK) rows[t] = g_row[b*KK + t];
    __syncthreads();

    int g = lane >> 3, r = lane & 7;
    uint32_t a_off = (uint32_t)((wr*16 + ((g & 1) << 3) + r)*(GTS*2) + (((g >> 1) << 3) * 2));
    uint32_t b_off0 = (uint32_t)((wc*32 +      ((g >> 1) << 3) + r)*(GTS*2) + (((g & 1) << 3) * 2));
    uint32_t b_off1 = (uint32_t)((wc*32 + 16 + ((g >> 1) << 3) + r)*(GTS*2) + (((g & 1) << 3) * 2));

    float acc[4][4];
    #pragma unroll
    for (int ni = 0; ni < 4; ni++)
        #pragma unroll
        for (int q = 0; q < 4; q++) acc[ni][q] = 0.f;

    const int nch = DD >> 6;   // 32

    #pragma unroll
    for (int pre = 0; pre < 2; pre++) {
        int k0 = pre << 6;
        #pragma unroll
        for (int hl = 0; hl < 2; hl++) {
            const __nv_bfloat16* src = hl ? g_Ml : g_Mh;
            uint32_t sB = smem_u32(&buf[pre][hl][0]);
            #pragma unroll
            for (int i = 0; i < 2; i++) {
                int task = t + i*256;
                int row = task >> 3, c16 = task & 7;
                const __nv_bfloat16* ga = src + (size_t)rows[row]*DD + k0 + c16*8;
                CP_ASYNC16(sB + (uint32_t)(row*GTS*2 + c16*16), ga);
            }
        }
        CP_COMMIT();
    }

    for (int ch = 0; ch < nch; ch++) {
        if (ch == nch - 1) CP_WAIT0(); else CP_WAIT1();
        __syncthreads();
        uint32_t sH = smem_u32(&buf[ch & 1][0][0]);
        uint32_t sL = smem_u32(&buf[ch & 1][1][0]);

        #pragma unroll
        for (int ks = 0; ks < 4; ks++) {
            uint32_t kb = (uint32_t)(ks*32);
            uint32_t ah[4], al[4], bh[2][4], bl[2][4];
            LDMATRIX_X4(ah[0], ah[1], ah[2], ah[3], sH + a_off + kb);
            LDMATRIX_X4(al[0], al[1], al[2], al[3], sL + a_off + kb);
            LDMATRIX_X4(bh[0][0], bh[0][1], bh[0][2], bh[0][3], sH + b_off0 + kb);
            LDMATRIX_X4(bh[1][0], bh[1][1], bh[1][2], bh[1][3], sH + b_off1 + kb);
            LDMATRIX_X4(bl[0][0], bl[0][1], bl[0][2], bl[0][3], sL + b_off0 + kb);
            LDMATRIX_X4(bl[1][0], bl[1][1], bl[1][2], bl[1][3], sL + b_off1 + kb);
            #pragma unroll
            for (int ni = 0; ni < 4; ni++) {
                int nj = ni >> 1, h2 = (ni & 1)*2;
                MMA16816(acc[ni], ah, bh[nj][h2], bh[nj][h2+1]);
                MMA16816(acc[ni], ah, bl[nj][h2], bl[nj][h2+1]);
                MMA16816(acc[ni], al, bh[nj][h2], bh[nj][h2+1]);
            }
        }
        __syncthreads();
        if (ch + 2 < nch) {
            int k0 = (ch + 2) << 6;
            #pragma unroll
            for (int hl = 0; hl < 2; hl++) {
                const __nv_bfloat16* src = hl ? g_Ml : g_Mh;
                uint32_t sB = smem_u32(&buf[ch & 1][hl][0]);
                #pragma unroll
                for (int i = 0; i < 2; i++) {
                    int task = t + i*256;
                    int row = task >> 3, c16 = task & 7;
                    const __nv_bfloat16* ga = src + (size_t)rows[row]*DD + k0 + c16*8;
                    CP_ASYNC16(sB + (uint32_t)(row*GTS*2 + c16*16), ga);
                }
            }
            CP_COMMIT();
        }
    }

    float* Gb = g_G + (size_t)b*KK*KK;
    int rr0 = wr*16 + (lane >> 2);
    #pragma unroll
    for (int ni = 0; ni < 4; ni++) {
        int cc = wc*32 + ni*8 + (lane & 3)*2;
        float2 v0 = { acc[ni][0], acc[ni][1] };
        float2 v1 = { acc[ni][2], acc[ni][3] };
        *(float2*)&Gb[rr0*KK + cc]       = v0;
        *(float2*)&Gb[(rr0 + 8)*KK + cc] = v1;
    }
}

__global__ void k_buildA(const float* __restrict__ all_pred)
{
    __shared__ float red[KK];
    int b = blockIdx.x / KK;
    int k = blockIdx.x % KK;
    int j = threadIdx.x;
    float v = g_G[(size_t)b*KK*KK + k*KK + j] * expf(all_pred[(b*KK + j)*2 + 1]);
    red[j] = v;
    __syncthreads();
    for (int o = 32; o > 0; o >>= 1) {
        if (j < o) red[j] = fmaxf(red[j], red[j + o]);
        __syncthreads();
    }
    float mx = red[0];
    __syncthreads();
    float e = expf(v - mx);
    red[j] = e;
    __syncthreads();
    for (int o = 32; o > 0; o >>= 1) {
        if (j < o) red[j] += red[j + o];
        __syncthreads();
    }
    g_Adj[(size_t)b*KK*KK + k*KK + j] = e / red[0];
}

// ---------------- mma.sync pure-bf16 GEMM -------------------------------------

#define TSTRIDE 72
#define TILE_E  (128*TSTRIDE)
#define GEMM_SMEM (2*2*TILE_E*2)   // 73728 bytes

__global__ __launch_bounds__(256)
void k_mma_gemm(int Kd,
                const __nv_bfloat16* __restrict__ Ah,
                const __nv_bfloat16* __restrict__ Bh,
                float* __restrict__ C, int Ncols)
{
    extern __shared__ __nv_bfloat16 sm[];
    int t = threadIdx.x;
    int lane = t & 31, wid = t >> 5;
    int m0 = blockIdx.y*128, n0 = blockIdx.x*128;
    int wm = (wid & 3) * 32;
    int wn = (wid >> 2) * 64;

    uint32_t sbase = smem_u32(sm);
    int lrow = t >> 3;
    int c16  = t & 7;
    const __nv_bfloat16* gA = Ah + (size_t)m0*Kd;
    const __nv_bfloat16* gB = Bh + (size_t)n0*Kd;

    int nch = Kd >> 6;

    int g = lane >> 3, r = lane & 7;
    uint32_t a_row  = wm + ((g & 1) << 3) + r;
    uint32_t a_colB = (uint32_t)(((g >> 1) << 3) * 2);
    uint32_t b_row  = wn + ((g >> 1) << 3) + r;
    uint32_t b_colB = (uint32_t)(((g & 1) << 3) * 2);

    float acc[2][8][4];
    #pragma unroll
    for (int mi = 0; mi < 2; mi++)
        #pragma unroll
        for (int ni = 0; ni < 8; ni++)
            #pragma unroll
            for (int q = 0; q < 4; q++) acc[mi][ni][q] = 0.f;

    #pragma unroll
    for (int pre = 0; pre < 2; pre++) {
        uint32_t sb = sbase + (uint32_t)pre*(2*TILE_E*2);
        int k0 = pre << 6;
        #pragma unroll
        for (int i = 0; i < 4; i++) {
            int rr = lrow + i*32;
            size_t go = (size_t)rr*Kd + k0 + c16*8;
            uint32_t so = (uint32_t)(rr*TSTRIDE)*2 + (uint32_t)c16*16;
            CP_ASYNC16(sb + so, gA + go);
            CP_ASYNC16(sb + TILE_E*2 + so, gB + go);
        }
        CP_COMMIT();
    }

    for (int ch = 0; ch < nch; ch++) {
        if (ch == nch - 1) CP_WAIT0(); else CP_WAIT1();
        __syncthreads();

        uint32_t sb  = sbase + (uint32_t)(ch & 1)*(2*TILE_E*2);
        uint32_t sA = sb;
        uint32_t sB = sb + TILE_E*2;

        #pragma unroll
        for (int ks = 0; ks < 4; ks++) {
            uint32_t kb = (uint32_t)(ks*32);
            uint32_t ah[2][4];
            #pragma unroll
            for (int mi = 0; mi < 2; mi++) {
                uint32_t ra = (a_row + mi*16)*(TSTRIDE*2) + a_colB + kb;
                LDMATRIX_X4(ah[mi][0], ah[mi][1], ah[mi][2], ah[mi][3], sA + ra);
            }
            uint32_t bh[4][4];
            #pragma unroll
            for (int nj = 0; nj < 4; nj++) {
                uint32_t rb = (b_row + nj*16)*(TSTRIDE*2) + b_colB + kb;
                LDMATRIX_X4(bh[nj][0], bh[nj][1], bh[nj][2], bh[nj][3], sB + rb);
            }
            #pragma unroll
            for (int mi = 0; mi < 2; mi++)
                #pragma unroll
                for (int ni = 0; ni < 8; ni++) {
                    int nj = ni >> 1, h = (ni & 1) * 2;
                    MMA16816(acc[mi][ni], ah[mi], bh[nj][h], bh[nj][h+1]);
                }
        }
        __syncthreads();
        if (ch + 2 < nch) {
            uint32_t sb2 = sbase + (uint32_t)(ch & 1)*(2*TILE_E*2);
            int k0 = (ch + 2) << 6;
            #pragma unroll
            for (int i = 0; i < 4; i++) {
                int rr = lrow + i*32;
                size_t go = (size_t)rr*Kd + k0 + c16*8;
                uint32_t so = (uint32_t)(rr*TSTRIDE)*2 + (uint32_t)c16*16;
                CP_ASYNC16(sb2 + so, gA + go);
                CP_ASYNC16(sb2 + TILE_E*2 + so, gB + go);
            }
            CP_COMMIT();
        }
    }

    #pragma unroll
    for (int mi = 0; mi < 2; mi++) {
        int rr0 = m0 + wm + mi*16 + (lane >> 2);
        #pragma unroll
        for (int ni = 0; ni < 8; ni++) {
            int cc = n0 + wn + ni*8 + (lane & 3)*2;
            float2 v0 = { acc[mi][ni][0], acc[mi][ni][1] };
            float2 v1 = { acc[mi][ni][2], acc[mi][ni][3] };
            *(float2*)&C[(size_t)rr0*Ncols + cc]       = v0;
            *(float2*)&C[(size_t)(rr0 + 8)*Ncols + cc] = v1;
        }
    }
}

// gemm3 + fused head: Hc tile stays in registers; epilogue applies bc1 + PReLU,
// multiplies by Wc2, reduces per-row partials in smem, writes per-colblock slot.
__global__ __launch_bounds__(256)
void k_mma_gemm_head(const __nv_bfloat16* __restrict__ Ah,
                     const __nv_bfloat16* __restrict__ Bh,
                     const float* __restrict__ bc1,
                     const float* __restrict__ prelu_a,
                     const float* __restrict__ Wc2)
{
    extern __shared__ __nv_bfloat16 sm[];
    const int Kd = HH2;   // 256
    int t = threadIdx.x;
    int lane = t & 31, wid = t >> 5;
    int m0 = blockIdx.y*128, n0 = blockIdx.x*128;
    int wm = (wid & 3) * 32;
    int wn = (wid >> 2) * 64;

    uint32_t sbase = smem_u32(sm);
    int lrow = t >> 3;
    int c16  = t & 7;
    const __nv_bfloat16* gA = Ah + (size_t)m0*Kd;
    const __nv_bfloat16* gB = Bh + (size_t)n0*Kd;

    const int nch = Kd >> 6;  // 4

    int g = lane >> 3, r = lane & 7;
    uint32_t a_row  = wm + ((g & 1) << 3) + r;
    uint32_t a_colB = (uint32_t)(((g >> 1) << 3) * 2);
    uint32_t b_row  = wn + ((g >> 1) << 3) + r;
    uint32_t b_colB = (uint32_t)(((g & 1) << 3) * 2);

    float acc[2][8][4];
    #pragma unroll
    for (int mi = 0; mi < 2; mi++)
        #pragma unroll
        for (int ni = 0; ni < 8; ni++)
            #pragma unroll
            for (int q = 0; q < 4; q++) acc[mi][ni][q] = 0.f;

    #pragma unroll
    for (int pre = 0; pre < 2; pre++) {
        uint32_t sb = sbase + (uint32_t)pre*(2*TILE_E*2);
        int k0 = pre << 6;
        #pragma unroll
        for (int i = 0; i < 4; i++) {
            int rr = lrow + i*32;
            size_t go = (size_t)rr*Kd + k0 + c16*8;
            uint32_t so = (uint32_t)(rr*TSTRIDE)*2 + (uint32_t)c16*16;
            CP_ASYNC16(sb + so, gA + go);
            CP_ASYNC16(sb + TILE_E*2 + so, gB + go);
        }
        CP_COMMIT();
    }

    for (int ch = 0; ch < nch; ch++) {
        if (ch == nch - 1) CP_WAIT0(); else CP_WAIT1();
        __syncthreads();

        uint32_t sb  = sbase + (uint32_t)(ch & 1)*(2*TILE_E*2);
        uint32_t sA = sb;
        uint32_t sB = sb + TILE_E*2;

        #pragma unroll
        for (int ks = 0; ks < 4; ks++) {
            uint32_t kb = (uint32_t)(ks*32);
            uint32_t ah[2][4];
            #pragma unroll
            for (int mi = 0; mi < 2; mi++) {
                uint32_t ra = (a_row + mi*16)*(TSTRIDE*2) + a_colB + kb;
                LDMATRIX_X4(ah[mi][0], ah[mi][1], ah[mi][2], ah[mi][3], sA + ra);
            }
            uint32_t bh[4][4];
            #pragma unroll
            for (int nj = 0; nj < 4; nj++) {
                uint32_t rb = (b_row + nj*16)*(TSTRIDE*2) + b_colB + kb;
                LDMATRIX_X4(bh[nj][0], bh[nj][1], bh[nj][2], bh[nj][3], sB + rb);
            }
            #pragma unroll
            for (int mi = 0; mi < 2; mi++)
                #pragma unroll
                for (int ni = 0; ni < 8; ni++) {
                    int nj = ni >> 1, h = (ni & 1) * 2;
                    MMA16816(acc[mi][ni], ah[mi], bh[nj][h], bh[nj][h+1]);
                }
        }
        __syncthreads();
        if (ch + 2 < nch) {
            uint32_t sb2 = sbase + (uint32_t)(ch & 1)*(2*TILE_E*2);
            int k0 = (ch + 2) << 6;
            #pragma unroll
            for (int i = 0; i < 4; i++) {
                int rr = lrow + i*32;
                size_t go = (size_t)rr*Kd + k0 + c16*8;
                uint32_t so = (uint32_t)(rr*TSTRIDE)*2 + (uint32_t)c16*16;
                CP_ASYNC16(sb2 + so, gA + go);
                CP_ASYNC16(sb2 + TILE_E*2 + so, gB + go);
            }
            CP_COMMIT();
        }
    }

    // fused head epilogue: per-thread partial sums s[localrow][class]
    float s[4][2];
    #pragma unroll
    for (int i = 0; i < 4; i++) { s[i][0] = 0.f; s[i][1] = 0.f; }

    #pragma unroll
    for (int ni = 0; ni < 8; ni++) {
        int cc = n0 + wn + ni*8 + (lane & 3)*2;
        #pragma unroll
        for (int q = 0; q < 2; q++) {
            int c = cc + q;
            float b1v = bc1[c], av = prelu_a[c];
            float w0 = Wc2[2*c], w1 = Wc2[2*c + 1];
            #pragma unroll
            for (int mi = 0; mi < 2; mi++) {
                float hlo = acc[mi][ni][q] + b1v;
                hlo = (hlo >= 0.f) ? hlo : av*hlo;
                s[mi*2 + 0][0] += hlo*w0;
                s[mi*2 + 0][1] += hlo*w1;
                float hhi = acc[mi][ni][2 + q] + b1v;
                hhi = (hhi >= 0.f) ? hhi : av*hhi;
                s[mi*2 + 1][0] += hhi*w0;
                s[mi*2 + 1][1] += hhi*w1;
            }
        }
    }
    // reduce across the 4 lanes sharing each row
    #pragma unroll
    for (int i = 0; i < 4; i++) {
        #pragma unroll
        for (int cl = 0; cl < 2; cl++) {
            s[i][cl] += __shfl_xor_sync(0xFFFFFFFFu, s[i][cl], 1);
            s[i][cl] += __shfl_xor_sync(0xFFFFFFFFu, s[i][cl], 2);
        }
    }
    // cross-warp (wn) combination in smem: hred[wn][local row 0..127][class]
    __shared__ float hred[2][128][2];
    if ((lane & 3) == 0) {
        int wnb = wid >> 2;
        int lr = wm + (lane >> 2);
        hred[wnb][lr      ][0] = s[0][0];  hred[wnb][lr      ][1] = s[0][1];
        hred[wnb][lr +  8 ][0] = s[1][0];  hred[wnb][lr +  8 ][1] = s[1][1];
        hred[wnb][lr + 16 ][0] = s[2][0];  hred[wnb][lr + 16 ][1] = s[2][1];
        hred[wnb][lr + 24 ][0] = s[3][0];  hred[wnb][lr + 24 ][1] = s[3][1];
    }
    __syncthreads();
    {
        int lr = t >> 1, cl = t & 1;
        g_part[blockIdx.x][(size_t)(m0 + lr)*2 + cl] =
            hred[0][lr][cl] + hred[1][lr][cl];
    }
}

// ---------------- combines ----------------------------------------------------

__global__ __launch_bounds__(256)
void k_combine1(const float* __restrict__ bias)
{
    __shared__ float As[KK][KK];
    __shared__ float Bs[32][128];
    __shared__ int   rows[KK];
    int b    = blockIdx.y;
    int col0 = blockIdx.x * 128;
    int t = threadIdx.x;
    int tx = t & 15, ty = t >> 4;

    const float* Ab = g_Adj + (size_t)b*KK*KK;
    for (int idx = t; idx < KK*KK; idx += 256)
        As[idx >> 6][idx & 63] = Ab[idx];
    if (t < KK) rows[t] = g_row[b*KK + t];
    __syncthreads();

    int piv = CC + b;
    int cc  = col0 + tx*8;
    const float* Up = g_U + (size_t)piv*1024;
    float4 upa = *(const float4*)(Up + cc);
    float4 upb = *(const float4*)(Up + cc + 4);
    float4 uba = *(const float4*)(Up + 512 + cc);
    float4 ubb = *(const float4*)(Up + 512 + cc + 4);
    float up[8] = {upa.x,upa.y,upa.z,upa.w,upb.x,upb.y,upb.z,upb.w};
    float ub[8] = {uba.x,uba.y,uba.z,uba.w,ubb.x,ubb.y,ubb.z,ubb.w};

    float acc[4][8];
    #pragma unroll
    for (int i = 0; i < 4; i++)
        #pragma unroll
        for (int c = 0; c < 8; c++) acc[i][c] = 0.f;

    for (int jt = 0; jt < KK; jt += 32) {
        #pragma unroll
        for (int i = 0; i < 4; i++) {
            int idx = t + i*256;
            int j = idx >> 5, c4 = idx & 31;
            *(float4*)&Bs[j][c4*4] =
                *(const float4*)(g_U + (size_t)rows[jt + j]*1024 + 512 + col0 + c4*4);
        }
        __syncthreads();
        #pragma unroll 4
        for (int j = 0; j < 32; j++) {
            float a[4];
            #pragma unroll
            for (int i = 0; i < 4; i++) a[i] = As[ty*4 + i][jt + j];
            float4 b0 = *(const float4*)&Bs[j][tx*8];
            float4 b1 = *(const float4*)&Bs[j][tx*8 + 4];
            float bf[8] = {b0.x,b0.y,b0.z,b0.w,b1.x,b1.y,b1.z,b1.w};
            #pragma unroll
            for (int i = 0; i < 4; i++)
                #pragma unroll
                for (int c = 0; c < 8; c++)
                    acc[i][c] = fmaf(a[i], bf[c], acc[i][c]);
        }
        __syncthreads();
    }
    #pragma unroll
    for (int i = 0; i < 4; i++) {
        int k = ty*4 + i;
        size_t m = (size_t)(b*KK + k);
        const float* ut = g_U + (size_t)rows[k]*1024 + cc;
        float4 t0 = *(const float4*)ut;
        float4 t1 = *(const float4*)(ut + 4);
        float uv[8] = {t0.x,t0.y,t0.z,t0.w,t1.x,t1.y,t1.z,t1.w};
        #pragma unroll
        for (int c = 0; c < 8; c++) {
            float v = acc[i][c] + uv[c] - up[c] - ub[c] + bias[cc + c];
            g_X1h[m*NHID + cc + c] = __float2bfloat16(fmaxf(v, 0.f));
        }
    }
}

__global__ __launch_bounds__(256)
void k_combine2(const float* __restrict__ bias)
{
    __shared__ float As[KK][KK];
    __shared__ float Bs[32][128];
    int b    = blockIdx.y;
    int col0 = blockIdx.x * 128;
    int t = threadIdx.x;
    int tx = t & 15, ty = t >> 4;

    const float* Ab = g_Adj + (size_t)b*KK*KK;
    for (int idx = t; idx < KK*KK; idx += 256)
        As[idx >> 6][idx & 63] = Ab[idx];

    float acc[4][8];
    #pragma unroll
    for (int i = 0; i < 4; i++)
        #pragma unroll
        for (int c = 0; c < 8; c++) acc[i][c] = 0.f;

    for (int jt = 0; jt < KK; jt += 32) {
        __syncthreads();
        #pragma unroll
        for (int i = 0; i < 4; i++) {
            int idx = t + i*256;
            int j = idx >> 5, c4 = idx & 31;
            *(float4*)&Bs[j][c4*4] =
                *(const float4*)(g_Z + (size_t)(b*KK + jt + j)*512 + 256 + col0 + c4*4);
        }
        __syncthreads();
        #pragma unroll 4
        for (int j = 0; j < 32; j++) {
            float a[4];
            #pragma unroll
            for (int i = 0; i < 4; i++) a[i] = As[ty*4 + i][jt + j];
            float4 b0 = *(const float4*)&Bs[j][tx*8];
            float4 b1 = *(const float4*)&Bs[j][tx*8 + 4];
            float bf[8] = {b0.x,b0.y,b0.z,b0.w,b1.x,b1.y,b1.z,b1.w};
            #pragma unroll
            for (int i = 0; i < 4; i++)
                #pragma unroll
                for (int c = 0; c < 8; c++)
                    acc[i][c] = fmaf(a[i], bf[c], acc[i][c]);
        }
    }
    #pragma unroll
    for (int i = 0; i < 4; i++) {
        size_t m = (size_t)(b*KK + ty*4 + i);
        #pragma unroll
        for (int c = 0; c < 8; c++) {
            int cc = col0 + tx*8 + c;
            float v = acc[i][c] + g_Z[m*512 + cc] + bias[cc];
            g_X2h[m*HH2 + cc] = __float2bfloat16(fmaxf(v, 0.f));
        }
    }
}

// softmax finalize over the two per-colblock partials
__global__ void k_headfin(const float* __restrict__ bc2,
                          float* __restrict__ pred_out)
{
    int m = blockIdx.x*blockDim.x + threadIdx.x;
    if (m >= MM) return;
    float l0 = g_part[0][2*m]     + g_part[1][2*m]     + bc2[0];
    float l1 = g_part[0][2*m + 1] + g_part[1][2*m + 1] + bc2[1];
    float mx = fmaxf(l0, l1);
    float e0 = expf(l0 - mx), e1 = expf(l1 - mx);
    float inv = 1.0f / (e0 + e1);
    pred_out[2*m]     = e0*inv;
    pred_out[2*m + 1] = e1*inv;
}

// ---------------- launch -----------------------------------------------------

extern "C" void kernel_launch(void* const* d_in, const int* in_sizes, int n_in,
                              void* d_out, int out_size)
{
    const int*   indexes  = (const int*)  d_in[0];
    const float* features = (const float*)d_in[1];
    const int*   labels   = (const int*)  d_in[2];
    const int*   knn      = (const int*)  d_in[5];
    const float* all_pred = (const float*)d_in[6];
    const float* W1  = (const float*)d_in[7];
    const float* b1  = (const float*)d_in[8];
    const float* W2  = (const float*)d_in[9];
    const float* b2  = (const float*)d_in[10];
    const float* Wc1 = (const float*)d_in[11];
    const float* bc1 = (const float*)d_in[12];
    const float* pa  = (const float*)d_in[13];
    const float* Wc2 = (const float*)d_in[14];
    const float* bc2 = (const float*)d_in[15];

    float* out = (float*)d_out;
    float* pred_out = out;
    float* simm_out = out + (size_t)MM*2;

    cudaFuncSetAttribute(k_mma_gemm, cudaFuncAttributeMaxDynamicSharedMemorySize,
                         GEMM_SMEM);
    cudaFuncSetAttribute(k_mma_gemm_head, cudaFuncAttributeMaxDynamicSharedMemorySize,
                         GEMM_SMEM);

    __nv_bfloat16 *pA1h,*pW1h,*pW2h,*pWch,*pX1h,*pX2h;
    float *pU,*pZ;
    cudaGetSymbolAddress((void**)&pA1h, g_A1h);
    cudaGetSymbolAddress((void**)&pW1h, g_W1h);
    cudaGetSymbolAddress((void**)&pW2h, g_W2h);
    cudaGetSymbolAddress((void**)&pWch, g_Wch);
    cudaGetSymbolAddress((void**)&pX1h, g_X1h);
    cudaGetSymbolAddress((void**)&pX2h, g_X2h);
    cudaGetSymbolAddress((void**)&pU,  g_U);
    cudaGetSymbolAddress((void**)&pZ,  g_Z);

    // ---- fork S1: rowmap + weight conversions (off critical path) ----
    cudaEventRecord(g_evF1, 0);
    cudaStreamWaitEvent(g_s1, g_evF1, 0);
    k_rowmap<<<(MM + 255)/256, 256, 0, g_s1>>>(labels, knn);
    cudaEventRecord(g_evR, g_s1);
    k_convW<<<(1024u*DD)/256, 256, 0, g_s1>>>(W1, NHID, DD, NHID, pW1h);
    k_convW<<<(512u*NHID)/256, 256, 0, g_s1>>>(W2, HH2, NHID, HH2, pW2h);
    k_convW<<<(HH2*HH2)/256, 256, 0, g_s1>>>(Wc1, HH2, HH2, HH2, pWch);
    cudaEventRecord(g_evW, g_s1);

    // ---- legacy: cluster chain (g_icnt zeroed at tail of previous replay) ----
    k_count<<<(NPTS/4 + 255)/256, 256>>>(labels);
    k_scan<<<1, 256>>>();
    k_scatter<<<(NPTS/4 + 255)/256, 256>>>(labels);
    k_cmean<<<CC + BB, 256>>>(features, indexes, simm_out);
    cudaEventRecord(g_evF2, 0);

    // S1 tail: zero g_icnt for next replay (after cmean consumed it)
    cudaStreamWaitEvent(g_s1, g_evF2, 0);
    k_zeroc<<<(CC + 255)/256, 256, 0, g_s1>>>();
    cudaEventRecord(g_evZ, g_s1);

    // ---- fork S2: gram + adjacency (overlaps layer-1 GEMM) ----
    cudaStreamWaitEvent(g_s2, g_evF2, 0);
    cudaStreamWaitEvent(g_s2, g_evR, 0);
    k_gram_mma<<<BB, 256, 0, g_s2>>>();
    k_buildA<<<BB*KK, KK, 0, g_s2>>>(all_pred);
    cudaEventRecord(g_evG, g_s2);

    // ---- legacy: layer 1 GEMM (needs cmean + convW) ----
    cudaStreamWaitEvent(0, g_evW, 0);
    k_mma_gemm<<<dim3(1024/128, MU/128), 256, GEMM_SMEM>>>(DD, pA1h, pW1h, pU, 1024);

    // join gram branch, then combine + rest
    cudaStreamWaitEvent(0, g_evG, 0);
    k_combine1<<<dim3(NHID/128, BB), 256>>>(b1);
    k_mma_gemm<<<dim3(512/128, MM/128), 256, GEMM_SMEM>>>(NHID, pX1h, pW2h, pZ, 512);
    k_combine2<<<dim3(HH2/128, BB), 256>>>(b2);
    k_mma_gemm_head<<<dim3(HH2/128, MM/128), 256, GEMM_SMEM>>>(pX2h, pWch, bc1, pa, Wc2);
    cudaStreamWaitEvent(0, g_evZ, 0);
    k_headfin<<<(MM + 255)/256, 256>>>(bc2, pred_out);

    (void)in_sizes; (void)n_in; (void)out_size;
}

// round 17
// speedup vs baseline: 1.0357x; 1.0357x over previous
#include <cuda_runtime.h>
#include <cuda_bf16.h>
#include <math.h>
#include <stdint.h>

#define BB   256
#define KK   64
#define DD   2048
#define NPTS 50000
#define CC   5000
#define NHID 512
#define HH2  256
#define MM   (BB*KK)        // 16384
#define MU   5376           // padded unique rows: 5000 clusters + 256 pivots + pad

// ---------------- scratch (device globals; no allocations allowed) ----------
__device__ int   g_icnt[CC];
__device__ int   g_off[CC];
__device__ int   g_wptr[CC];
__device__ int   g_sidx[NPTS];
__device__ __nv_bfloat16 g_Mh[(size_t)MU*DD];    // UNnormalized rows hi/lo (gram)
__device__ __nv_bfloat16 g_Ml[(size_t)MU*DD];
__device__ __nv_bfloat16 g_A1h[(size_t)MU*DD];   // normalized rows (layer1 input)
__device__ __nv_bfloat16 g_W1h[(size_t)1024*DD]; // W1^T fused [1024 x 2048]
__device__ __nv_bfloat16 g_W2h[(size_t)512*NHID];
__device__ __nv_bfloat16 g_Wch[(size_t)HH2*HH2];
__device__ float g_U [(size_t)MU*1024];          // layer1 unique-row outputs [top|bot]
__device__ __nv_bfloat16 g_X1h[(size_t)MM*NHID];
__device__ float g_Z [(size_t)MM*NHID];          // layer2 outputs [top|bot] per row
__device__ __nv_bfloat16 g_X2h[(size_t)MM*HH2];
__device__ float g_part[2][(size_t)MM*2];        // fused-head partials per col-block
__device__ float g_G  [(size_t)BB*KK*KK];
__device__ float g_Adj[(size_t)BB*KK*KK];
__device__ int   g_row[MM];

// ---------------- streams/events for graph-level parallelism -----------------
static cudaStream_t g_s1, g_s2;
static cudaEvent_t  g_evF1, g_evF2, g_evW, g_evG, g_evZ;
static int g_async_init = [](){
    cudaStreamCreateWithFlags(&g_s1, cudaStreamNonBlocking);
    cudaStreamCreateWithFlags(&g_s2, cudaStreamNonBlocking);
    cudaEventCreateWithFlags(&g_evF1, cudaEventDisableTiming);
    cudaEventCreateWithFlags(&g_evF2, cudaEventDisableTiming);
    cudaEventCreateWithFlags(&g_evW,  cudaEventDisableTiming);
    cudaEventCreateWithFlags(&g_evG,  cudaEventDisableTiming);
    cudaEventCreateWithFlags(&g_evZ,  cudaEventDisableTiming);
    return 0;
}();

// ---------------- helpers -----------------------------------------------------

__device__ __forceinline__ uint32_t smem_u32(const void* p) {
    uint32_t a;
    asm("{ .reg .u64 t; cvta.to.shared.u64 t, %1; cvt.u32.u64 %0, t; }"
        : "=r"(a) : "l"(p));
    return a;
}

#define CP_ASYNC16(saddr, gaddr) \
    asm volatile("cp.async.cg.shared.global [%0], [%1], 16;\n" \
                 :: "r"(saddr), "l"(gaddr))
#define CP_COMMIT() asm volatile("cp.async.commit_group;\n" ::: "memory")
#define CP_WAIT0()  asm volatile("cp.async.wait_group 0;\n" ::: "memory")
#define CP_WAIT1()  asm volatile("cp.async.wait_group 1;\n" ::: "memory")

#define LDMATRIX_X4(d0,d1,d2,d3, addr) \
    asm volatile("ldmatrix.sync.aligned.m8n8.x4.shared.b16 {%0,%1,%2,%3}, [%4];\n" \
        : "=r"(d0), "=r"(d1), "=r"(d2), "=r"(d3) : "r"(addr))

#define MMA16816(c, a, b0v, b1v) \
    asm volatile("mma.sync.aligned.m16n8k16.row.col.f32.bf16.bf16.f32 " \
        "{%0,%1,%2,%3}, {%4,%5,%6,%7}, {%8,%9}, {%0,%1,%2,%3};\n" \
        : "+f"((c)[0]), "+f"((c)[1]), "+f"((c)[2]), "+f"((c)[3]) \
        : "r"((a)[0]), "r"((a)[1]), "r"((a)[2]), "r"((a)[3]), \
          "r"(b0v), "r"(b1v))

// ---------------- cluster-mean pipeline (sorted, no big atomics) --------------

__global__ void k_zeroc()
{
    int i = blockIdx.x*blockDim.x + threadIdx.x;
    if (i < CC) g_icnt[i] = 0;
}

// int4-vectorized histogram (NPTS divisible by 4)
__global__ void k_count(const int* __restrict__ labels)
{
    int i = blockIdx.x*blockDim.x + threadIdx.x;
    if (i < NPTS/4) {
        int4 l = ((const int4*)labels)[i];
        atomicAdd(&g_icnt[l.x], 1);
        atomicAdd(&g_icnt[l.y], 1);
        atomicAdd(&g_icnt[l.z], 1);
        atomicAdd(&g_icnt[l.w], 1);
    }
}

// exclusive prefix over CC counts, single block of 256
__global__ void k_scan()
{
    __shared__ int wsum[8];
    int t = threadIdx.x, lane = t & 31, w = t >> 5;
    int local[20];
    int s = 0;
    #pragma unroll
    for (int j = 0; j < 20; j++) {
        int c = t*20 + j;
        int v = (c < CC) ? g_icnt[c] : 0;
        local[j] = s;
        s += v;
    }
    int x = s;
    #pragma unroll
    for (int o = 1; o < 32; o <<= 1) {
        int y = __shfl_up_sync(0xFFFFFFFFu, x, o);
        if (lane >= o) x += y;
    }
    if (lane == 31) wsum[w] = x;
    __syncthreads();
    if (t == 0) {
        int acc = 0;
        #pragma unroll
        for (int i = 0; i < 8; i++) { int v = wsum[i]; wsum[i] = acc; acc += v; }
    }
    __syncthreads();
    int base = wsum[w] + (x - s);
    #pragma unroll
    for (int j = 0; j < 20; j++) {
        int c = t*20 + j;
        if (c < CC) { g_off[c] = base + local[j]; g_wptr[c] = base + local[j]; }
    }
}

__global__ void k_scatter(const int* __restrict__ labels)
{
    int i = blockIdx.x*blockDim.x + threadIdx.x;
    if (i < NPTS) {
        int pos = atomicAdd(&g_wptr[labels[i]], 1);
        g_sidx[pos] = i;
    }
}

// rows [0,CC): cluster mean; rows [CC,CC+BB): pivot features.
__global__ __launch_bounds__(256)
void k_cmean(const float* __restrict__ feats,
             const int* __restrict__ indexes,
             float* __restrict__ simm_out)
{
    __shared__ float red[256];
    int c = blockIdx.x, t = threadIdx.x;
    float4 s0 = {0,0,0,0}, s1 = {0,0,0,0};
    float invn;
    if (c < CC) {
        int n = g_icnt[c], base = g_off[c];
        for (int r = 0; r < n; r++) {
            const float4* f = (const float4*)(feats + (size_t)g_sidx[base + r]*DD);
            float4 a = f[t], b = f[t + 256];
            s0.x += a.x; s0.y += a.y; s0.z += a.z; s0.w += a.w;
            s1.x += b.x; s1.y += b.y; s1.z += b.z; s1.w += b.w;
        }
        invn = 1.0f / (float)max(n, 1);
    } else {
        const float4* f = (const float4*)(feats + (size_t)indexes[c - CC]*DD);
        s0 = f[t]; s1 = f[t + 256];
        invn = 1.0f;
    }
    float m[8] = { s0.x*invn, s0.y*invn, s0.z*invn, s0.w*invn,
                   s1.x*invn, s1.y*invn, s1.z*invn, s1.w*invn };
    float ss = 0.f;
    #pragma unroll
    for (int j = 0; j < 8; j++) ss += m[j]*m[j];
    red[t] = ss;
    __syncthreads();
    for (int o = 128; o > 0; o >>= 1) {
        if (t < o) red[t] += red[t + o];
        __syncthreads();
    }
    float s = red[0];
    if (c < CC && t == 0) simm_out[c] = s;
    float inv = (s > 0.f) ? rsqrtf(s) : 0.f;
    size_t rb = (size_t)c*DD;
    #pragma unroll
    for (int j = 0; j < 8; j++) {
        int d = (j < 4) ? (t*4 + j) : (1024 + t*4 + (j - 4));
        float v = m[j];
        __nv_bfloat16 h = __float2bfloat16(v);
        g_Mh[rb + d] = h;
        g_Ml[rb + d] = __float2bfloat16(v - __bfloat162float(h));
        g_A1h[rb + d] = __float2bfloat16(v*inv);
    }
}

__global__ void k_rowmap(const int* __restrict__ labels,
                         const int* __restrict__ knn)
{
    int i = blockIdx.x*blockDim.x + threadIdx.x;
    if (i >= MM) return;
    int b = i / KK, k = i % KK;
    g_row[i] = (k == 0) ? (CC + b) : labels[knn[i]];
}

// weight transpose + bf16 (hi only)
__global__ void k_convW(const float* __restrict__ W, int ldw, int Kd, int Nh,
                        __nv_bfloat16* __restrict__ dh)
{
    size_t i = (size_t)blockIdx.x*blockDim.x + threadIdx.x;
    int n = (int)(i / Kd), k = (int)(i % Kd);
    int col  = (n < Nh) ? n : n - Nh;
    int koff = (n < Nh) ? 0 : Kd;
    dh[i] = __float2bfloat16(W[(size_t)(koff + k)*ldw + col]);
}

// ---------------- gram via mma (bf16x3, gathered rows) ------------------------

#define GTS 72   // smem row stride (elems)

__global__ __launch_bounds__(256)
void k_gram_mma()
{
    __shared__ int rows[KK];
    __shared__ __align__(16) __nv_bfloat16 buf[2][2][KK*GTS];
    int b = blockIdx.x, t = threadIdx.x;
    int lane = t & 31, wid = t >> 5;
    int wr = wid & 3, wc = wid >> 2;

    if (t < KK) rows[t] = g_row[b*KK + t];
    __syncthreads();

    int g = lane >> 3, r = lane & 7;
    uint32_t a_off = (uint32_t)((wr*16 + ((g & 1) << 3) + r)*(GTS*2) + (((g >> 1) << 3) * 2));
    uint32_t b_off0 = (uint32_t)((wc*32 +      ((g >> 1) << 3) + r)*(GTS*2) + (((g & 1) << 3) * 2));
    uint32_t b_off1 = (uint32_t)((wc*32 + 16 + ((g >> 1) << 3) + r)*(GTS*2) + (((g & 1) << 3) * 2));

    float acc[4][4];
    #pragma unroll
    for (int ni = 0; ni < 4; ni++)
        #pragma unroll
        for (int q = 0; q < 4; q++) acc[ni][q] = 0.f;

    const int nch = DD >> 6;   // 32

    #pragma unroll
    for (int pre = 0; pre < 2; pre++) {
        int k0 = pre << 6;
        #pragma unroll
        for (int hl = 0; hl < 2; hl++) {
            const __nv_bfloat16* src = hl ? g_Ml : g_Mh;
            uint32_t sB = smem_u32(&buf[pre][hl][0]);
            #pragma unroll
            for (int i = 0; i < 2; i++) {
                int task = t + i*256;
                int row = task >> 3, c16 = task & 7;
                const __nv_bfloat16* ga = src + (size_t)rows[row]*DD + k0 + c16*8;
                CP_ASYNC16(sB + (uint32_t)(row*GTS*2 + c16*16), ga);
            }
        }
        CP_COMMIT();
    }

    for (int ch = 0; ch < nch; ch++) {
        if (ch == nch - 1) CP_WAIT0(); else CP_WAIT1();
        __syncthreads();
        uint32_t sH = smem_u32(&buf[ch & 1][0][0]);
        uint32_t sL = smem_u32(&buf[ch & 1][1][0]);

        #pragma unroll
        for (int ks = 0; ks < 4; ks++) {
            uint32_t kb = (uint32_t)(ks*32);
            uint32_t ah[4], al[4], bh[2][4], bl[2][4];
            LDMATRIX_X4(ah[0], ah[1], ah[2], ah[3], sH + a_off + kb);
            LDMATRIX_X4(al[0], al[1], al[2], al[3], sL + a_off + kb);
            LDMATRIX_X4(bh[0][0], bh[0][1], bh[0][2], bh[0][3], sH + b_off0 + kb);
            LDMATRIX_X4(bh[1][0], bh[1][1], bh[1][2], bh[1][3], sH + b_off1 + kb);
            LDMATRIX_X4(bl[0][0], bl[0][1], bl[0][2], bl[0][3], sL + b_off0 + kb);
            LDMATRIX_X4(bl[1][0], bl[1][1], bl[1][2], bl[1][3], sL + b_off1 + kb);
            #pragma unroll
            for (int ni = 0; ni < 4; ni++) {
                int nj = ni >> 1, h2 = (ni & 1)*2;
                MMA16816(acc[ni], ah, bh[nj][h2], bh[nj][h2+1]);
                MMA16816(acc[ni], ah, bl[nj][h2], bl[nj][h2+1]);
                MMA16816(acc[ni], al, bh[nj][h2], bh[nj][h2+1]);
            }
        }
        __syncthreads();
        if (ch + 2 < nch) {
            int k0 = (ch + 2) << 6;
            #pragma unroll
            for (int hl = 0; hl < 2; hl++) {
                const __nv_bfloat16* src = hl ? g_Ml : g_Mh;
                uint32_t sB = smem_u32(&buf[ch & 1][hl][0]);
                #pragma unroll
                for (int i = 0; i < 2; i++) {
                    int task = t + i*256;
                    int row = task >> 3, c16 = task & 7;
                    const __nv_bfloat16* ga = src + (size_t)rows[row]*DD + k0 + c16*8;
                    CP_ASYNC16(sB + (uint32_t)(row*GTS*2 + c16*16), ga);
                }
            }
            CP_COMMIT();
        }
    }

    float* Gb = g_G + (size_t)b*KK*KK;
    int rr0 = wr*16 + (lane >> 2);
    #pragma unroll
    for (int ni = 0; ni < 4; ni++) {
        int cc = wc*32 + ni*8 + (lane & 3)*2;
        float2 v0 = { acc[ni][0], acc[ni][1] };
        float2 v1 = { acc[ni][2], acc[ni][3] };
        *(float2*)&Gb[rr0*KK + cc]       = v0;
        *(float2*)&Gb[(rr0 + 8)*KK + cc] = v1;
    }
}

__global__ void k_buildA(const float* __restrict__ all_pred)
{
    __shared__ float red[KK];
    int b = blockIdx.x / KK;
    int k = blockIdx.x % KK;
    int j = threadIdx.x;
    float v = g_G[(size_t)b*KK*KK + k*KK + j] * expf(all_pred[(b*KK + j)*2 + 1]);
    red[j] = v;
    __syncthreads();
    for (int o = 32; o > 0; o >>= 1) {
        if (j < o) red[j] = fmaxf(red[j], red[j + o]);
        __syncthreads();
    }
    float mx = red[0];
    __syncthreads();
    float e = expf(v - mx);
    red[j] = e;
    __syncthreads();
    for (int o = 32; o > 0; o >>= 1) {
        if (j < o) red[j] += red[j + o];
        __syncthreads();
    }
    g_Adj[(size_t)b*KK*KK + k*KK + j] = e / red[0];
}

// ---------------- mma.sync pure-bf16 GEMM -------------------------------------

#define TSTRIDE 72
#define TILE_E  (128*TSTRIDE)
#define GEMM_SMEM (2*2*TILE_E*2)   // 73728 bytes

__global__ __launch_bounds__(256)
void k_mma_gemm(int Kd,
                const __nv_bfloat16* __restrict__ Ah,
                const __nv_bfloat16* __restrict__ Bh,
                float* __restrict__ C, int Ncols)
{
    extern __shared__ __nv_bfloat16 sm[];
    int t = threadIdx.x;
    int lane = t & 31, wid = t >> 5;
    int m0 = blockIdx.y*128, n0 = blockIdx.x*128;
    int wm = (wid & 3) * 32;
    int wn = (wid >> 2) * 64;

    uint32_t sbase = smem_u32(sm);
    int lrow = t >> 3;
    int c16  = t & 7;
    const __nv_bfloat16* gA = Ah + (size_t)m0*Kd;
    const __nv_bfloat16* gB = Bh + (size_t)n0*Kd;

    int nch = Kd >> 6;

    int g = lane >> 3, r = lane & 7;
    uint32_t a_row  = wm + ((g & 1) << 3) + r;
    uint32_t a_colB = (uint32_t)(((g >> 1) << 3) * 2);
    uint32_t b_row  = wn + ((g >> 1) << 3) + r;
    uint32_t b_colB = (uint32_t)(((g & 1) << 3) * 2);

    float acc[2][8][4];
    #pragma unroll
    for (int mi = 0; mi < 2; mi++)
        #pragma unroll
        for (int ni = 0; ni < 8; ni++)
            #pragma unroll
            for (int q = 0; q < 4; q++) acc[mi][ni][q] = 0.f;

    #pragma unroll
    for (int pre = 0; pre < 2; pre++) {
        uint32_t sb = sbase + (uint32_t)pre*(2*TILE_E*2);
        int k0 = pre << 6;
        #pragma unroll
        for (int i = 0; i < 4; i++) {
            int rr = lrow + i*32;
            size_t go = (size_t)rr*Kd + k0 + c16*8;
            uint32_t so = (uint32_t)(rr*TSTRIDE)*2 + (uint32_t)c16*16;
            CP_ASYNC16(sb + so, gA + go);
            CP_ASYNC16(sb + TILE_E*2 + so, gB + go);
        }
        CP_COMMIT();
    }

    for (int ch = 0; ch < nch; ch++) {
        if (ch == nch - 1) CP_WAIT0(); else CP_WAIT1();
        __syncthreads();

        uint32_t sb  = sbase + (uint32_t)(ch & 1)*(2*TILE_E*2);
        uint32_t sA = sb;
        uint32_t sB = sb + TILE_E*2;

        #pragma unroll
        for (int ks = 0; ks < 4; ks++) {
            uint32_t kb = (uint32_t)(ks*32);
            uint32_t ah[2][4];
            #pragma unroll
            for (int mi = 0; mi < 2; mi++) {
                uint32_t ra = (a_row + mi*16)*(TSTRIDE*2) + a_colB + kb;
                LDMATRIX_X4(ah[mi][0], ah[mi][1], ah[mi][2], ah[mi][3], sA + ra);
            }
            uint32_t bh[4][4];
            #pragma unroll
            for (int nj = 0; nj < 4; nj++) {
                uint32_t rb = (b_row + nj*16)*(TSTRIDE*2) + b_colB + kb;
                LDMATRIX_X4(bh[nj][0], bh[nj][1], bh[nj][2], bh[nj][3], sB + rb);
            }
            #pragma unroll
            for (int mi = 0; mi < 2; mi++)
                #pragma unroll
                for (int ni = 0; ni < 8; ni++) {
                    int nj = ni >> 1, h = (ni & 1) * 2;
                    MMA16816(acc[mi][ni], ah[mi], bh[nj][h], bh[nj][h+1]);
                }
        }
        __syncthreads();
        if (ch + 2 < nch) {
            uint32_t sb2 = sbase + (uint32_t)(ch & 1)*(2*TILE_E*2);
            int k0 = (ch + 2) << 6;
            #pragma unroll
            for (int i = 0; i < 4; i++) {
                int rr = lrow + i*32;
                size_t go = (size_t)rr*Kd + k0 + c16*8;
                uint32_t so = (uint32_t)(rr*TSTRIDE)*2 + (uint32_t)c16*16;
                CP_ASYNC16(sb2 + so, gA + go);
                CP_ASYNC16(sb2 + TILE_E*2 + so, gB + go);
            }
            CP_COMMIT();
        }
    }

    #pragma unroll
    for (int mi = 0; mi < 2; mi++) {
        int rr0 = m0 + wm + mi*16 + (lane >> 2);
        #pragma unroll
        for (int ni = 0; ni < 8; ni++) {
            int cc = n0 + wn + ni*8 + (lane & 3)*2;
            float2 v0 = { acc[mi][ni][0], acc[mi][ni][1] };
            float2 v1 = { acc[mi][ni][2], acc[mi][ni][3] };
            *(float2*)&C[(size_t)rr0*Ncols + cc]       = v0;
            *(float2*)&C[(size_t)(rr0 + 8)*Ncols + cc] = v1;
        }
    }
}

// gemm3 + fused head: Hc tile stays in registers; epilogue applies bc1 + PReLU,
// multiplies by Wc2, reduces per-row partials in smem, writes per-colblock slot.
__global__ __launch_bounds__(256)
void k_mma_gemm_head(const __nv_bfloat16* __restrict__ Ah,
                     const __nv_bfloat16* __restrict__ Bh,
                     const float* __restrict__ bc1,
                     const float* __restrict__ prelu_a,
                     const float* __restrict__ Wc2)
{
    extern __shared__ __nv_bfloat16 sm[];
    const int Kd = HH2;   // 256
    int t = threadIdx.x;
    int lane = t & 31, wid = t >> 5;
    int m0 = blockIdx.y*128, n0 = blockIdx.x*128;
    int wm = (wid & 3) * 32;
    int wn = (wid >> 2) * 64;

    uint32_t sbase = smem_u32(sm);
    int lrow = t >> 3;
    int c16  = t & 7;
    const __nv_bfloat16* gA = Ah + (size_t)m0*Kd;
    const __nv_bfloat16* gB = Bh + (size_t)n0*Kd;

    const int nch = Kd >> 6;  // 4

    int g = lane >> 3, r = lane & 7;
    uint32_t a_row  = wm + ((g & 1) << 3) + r;
    uint32_t a_colB = (uint32_t)(((g >> 1) << 3) * 2);
    uint32_t b_row  = wn + ((g >> 1) << 3) + r;
    uint32_t b_colB = (uint32_t)(((g & 1) << 3) * 2);

    float acc[2][8][4];
    #pragma unroll
    for (int mi = 0; mi < 2; mi++)
        #pragma unroll
        for (int ni = 0; ni < 8; ni++)
            #pragma unroll
            for (int q = 0; q < 4; q++) acc[mi][ni][q] = 0.f;

    #pragma unroll
    for (int pre = 0; pre < 2; pre++) {
        uint32_t sb = sbase + (uint32_t)pre*(2*TILE_E*2);
        int k0 = pre << 6;
        #pragma unroll
        for (int i = 0; i < 4; i++) {
            int rr = lrow + i*32;
            size_t go = (size_t)rr*Kd + k0 + c16*8;
            uint32_t so = (uint32_t)(rr*TSTRIDE)*2 + (uint32_t)c16*16;
            CP_ASYNC16(sb + so, gA + go);
            CP_ASYNC16(sb + TILE_E*2 + so, gB + go);
        }
        CP_COMMIT();
    }

    for (int ch = 0; ch < nch; ch++) {
        if (ch == nch - 1) CP_WAIT0(); else CP_WAIT1();
        __syncthreads();

        uint32_t sb  = sbase + (uint32_t)(ch & 1)*(2*TILE_E*2);
        uint32_t sA = sb;
        uint32_t sB = sb + TILE_E*2;

        #pragma unroll
        for (int ks = 0; ks < 4; ks++) {
            uint32_t kb = (uint32_t)(ks*32);
            uint32_t ah[2][4];
            #pragma unroll
            for (int mi = 0; mi < 2; mi++) {
                uint32_t ra = (a_row + mi*16)*(TSTRIDE*2) + a_colB + kb;
                LDMATRIX_X4(ah[mi][0], ah[mi][1], ah[mi][2], ah[mi][3], sA + ra);
            }
            uint32_t bh[4][4];
            #pragma unroll
            for (int nj = 0; nj < 4; nj++) {
                uint32_t rb = (b_row + nj*16)*(TSTRIDE*2) + b_colB + kb;
                LDMATRIX_X4(bh[nj][0], bh[nj][1], bh[nj][2], bh[nj][3], sB + rb);
            }
            #pragma unroll
            for (int mi = 0; mi < 2; mi++)
                #pragma unroll
                for (int ni = 0; ni < 8; ni++) {
                    int nj = ni >> 1, h = (ni & 1) * 2;
                    MMA16816(acc[mi][ni], ah[mi], bh[nj][h], bh[nj][h+1]);
                }
        }
        __syncthreads();
        if (ch + 2 < nch) {
            uint32_t sb2 = sbase + (uint32_t)(ch & 1)*(2*TILE_E*2);
            int k0 = (ch + 2) << 6;
            #pragma unroll
            for (int i = 0; i < 4; i++) {
                int rr = lrow + i*32;
                size_t go = (size_t)rr*Kd + k0 + c16*8;
                uint32_t so = (uint32_t)(rr*TSTRIDE)*2 + (uint32_t)c16*16;
                CP_ASYNC16(sb2 + so, gA + go);
                CP_ASYNC16(sb2 + TILE_E*2 + so, gB + go);
            }
            CP_COMMIT();
        }
    }

    // fused head epilogue: per-thread partial sums s[localrow][class]
    float s[4][2];
    #pragma unroll
    for (int i = 0; i < 4; i++) { s[i][0] = 0.f; s[i][1] = 0.f; }

    #pragma unroll
    for (int ni = 0; ni < 8; ni++) {
        int cc = n0 + wn + ni*8 + (lane & 3)*2;
        #pragma unroll
        for (int q = 0; q < 2; q++) {
            int c = cc + q;
            float b1v = bc1[c], av = prelu_a[c];
            float w0 = Wc2[2*c], w1 = Wc2[2*c + 1];
            #pragma unroll
            for (int mi = 0; mi < 2; mi++) {
                float hlo = acc[mi][ni][q] + b1v;
                hlo = (hlo >= 0.f) ? hlo : av*hlo;
                s[mi*2 + 0][0] += hlo*w0;
                s[mi*2 + 0][1] += hlo*w1;
                float hhi = acc[mi][ni][2 + q] + b1v;
                hhi = (hhi >= 0.f) ? hhi : av*hhi;
                s[mi*2 + 1][0] += hhi*w0;
                s[mi*2 + 1][1] += hhi*w1;
            }
        }
    }
    // reduce across the 4 lanes sharing each row
    #pragma unroll
    for (int i = 0; i < 4; i++) {
        #pragma unroll
        for (int cl = 0; cl < 2; cl++) {
            s[i][cl] += __shfl_xor_sync(0xFFFFFFFFu, s[i][cl], 1);
            s[i][cl] += __shfl_xor_sync(0xFFFFFFFFu, s[i][cl], 2);
        }
    }
    // cross-warp (wn) combination in smem: hred[wn][local row 0..127][class]
    __shared__ float hred[2][128][2];
    if ((lane & 3) == 0) {
        int wnb = wid >> 2;
        int lr = wm + (lane >> 2);
        hred[wnb][lr      ][0] = s[0][0];  hred[wnb][lr      ][1] = s[0][1];
        hred[wnb][lr +  8 ][0] = s[1][0];  hred[wnb][lr +  8 ][1] = s[1][1];
        hred[wnb][lr + 16 ][0] = s[2][0];  hred[wnb][lr + 16 ][1] = s[2][1];
        hred[wnb][lr + 24 ][0] = s[3][0];  hred[wnb][lr + 24 ][1] = s[3][1];
    }
    __syncthreads();
    {
        int lr = t >> 1, cl = t & 1;
        g_part[blockIdx.x][(size_t)(m0 + lr)*2 + cl] =
            hred[0][lr][cl] + hred[1][lr][cl];
    }
}

// ---------------- combines ----------------------------------------------------

__global__ __launch_bounds__(256)
void k_combine1(const float* __restrict__ bias)
{
    __shared__ float As[KK][KK];
    __shared__ float Bs[32][128];
    __shared__ int   rows[KK];
    int b    = blockIdx.y;
    int col0 = blockIdx.x * 128;
    int t = threadIdx.x;
    int tx = t & 15, ty = t >> 4;

    const float* Ab = g_Adj + (size_t)b*KK*KK;
    for (int idx = t; idx < KK*KK; idx += 256)
        As[idx >> 6][idx & 63] = Ab[idx];
    if (t < KK) rows[t] = g_row[b*KK + t];
    __syncthreads();

    int piv = CC + b;
    int cc  = col0 + tx*8;
    const float* Up = g_U + (size_t)piv*1024;
    float4 upa = *(const float4*)(Up + cc);
    float4 upb = *(const float4*)(Up + cc + 4);
    float4 uba = *(const float4*)(Up + 512 + cc);
    float4 ubb = *(const float4*)(Up + 512 + cc + 4);
    float up[8] = {upa.x,upa.y,upa.z,upa.w,upb.x,upb.y,upb.z,upb.w};
    float ub[8] = {uba.x,uba.y,uba.z,uba.w,ubb.x,ubb.y,ubb.z,ubb.w};

    float acc[4][8];
    #pragma unroll
    for (int i = 0; i < 4; i++)
        #pragma unroll
        for (int c = 0; c < 8; c++) acc[i][c] = 0.f;

    for (int jt = 0; jt < KK; jt += 32) {
        #pragma unroll
        for (int i = 0; i < 4; i++) {
            int idx = t + i*256;
            int j = idx >> 5, c4 = idx & 31;
            *(float4*)&Bs[j][c4*4] =
                *(const float4*)(g_U + (size_t)rows[jt + j]*1024 + 512 + col0 + c4*4);
        }
        __syncthreads();
        #pragma unroll 4
        for (int j = 0; j < 32; j++) {
            float a[4];
            #pragma unroll
            for (int i = 0; i < 4; i++) a[i] = As[ty*4 + i][jt + j];
            float4 b0 = *(const float4*)&Bs[j][tx*8];
            float4 b1 = *(const float4*)&Bs[j][tx*8 + 4];
            float bf[8] = {b0.x,b0.y,b0.z,b0.w,b1.x,b1.y,b1.z,b1.w};
            #pragma unroll
            for (int i = 0; i < 4; i++)
                #pragma unroll
                for (int c = 0; c < 8; c++)
                    acc[i][c] = fmaf(a[i], bf[c], acc[i][c]);
        }
        __syncthreads();
    }
    #pragma unroll
    for (int i = 0; i < 4; i++) {
        int k = ty*4 + i;
        size_t m = (size_t)(b*KK + k);
        const float* ut = g_U + (size_t)rows[k]*1024 + cc;
        float4 t0 = *(const float4*)ut;
        float4 t1 = *(const float4*)(ut + 4);
        float uv[8] = {t0.x,t0.y,t0.z,t0.w,t1.x,t1.y,t1.z,t1.w};
        #pragma unroll
        for (int c = 0; c < 8; c++) {
            float v = acc[i][c] + uv[c] - up[c] - ub[c] + bias[cc + c];
            g_X1h[m*NHID + cc + c] = __float2bfloat16(fmaxf(v, 0.f));
        }
    }
}

__global__ __launch_bounds__(256)
void k_combine2(const float* __restrict__ bias)
{
    __shared__ float As[KK][KK];
    __shared__ float Bs[32][128];
    int b    = blockIdx.y;
    int col0 = blockIdx.x * 128;
    int t = threadIdx.x;
    int tx = t & 15, ty = t >> 4;

    const float* Ab = g_Adj + (size_t)b*KK*KK;
    for (int idx = t; idx < KK*KK; idx += 256)
        As[idx >> 6][idx & 63] = Ab[idx];

    float acc[4][8];
    #pragma unroll
    for (int i = 0; i < 4; i++)
        #pragma unroll
        for (int c = 0; c < 8; c++) acc[i][c] = 0.f;

    for (int jt = 0; jt < KK; jt += 32) {
        __syncthreads();
        #pragma unroll
        for (int i = 0; i < 4; i++) {
            int idx = t + i*256;
            int j = idx >> 5, c4 = idx & 31;
            *(float4*)&Bs[j][c4*4] =
                *(const float4*)(g_Z + (size_t)(b*KK + jt + j)*512 + 256 + col0 + c4*4);
        }
        __syncthreads();
        #pragma unroll 4
        for (int j = 0; j < 32; j++) {
            float a[4];
            #pragma unroll
            for (int i = 0; i < 4; i++) a[i] = As[ty*4 + i][jt + j];
            float4 b0 = *(const float4*)&Bs[j][tx*8];
            float4 b1 = *(const float4*)&Bs[j][tx*8 + 4];
            float bf[8] = {b0.x,b0.y,b0.z,b0.w,b1.x,b1.y,b1.z,b1.w};
            #pragma unroll
            for (int i = 0; i < 4; i++)
                #pragma unroll
                for (int c = 0; c < 8; c++)
                    acc[i][c] = fmaf(a[i], bf[c], acc[i][c]);
        }
    }
    #pragma unroll
    for (int i = 0; i < 4; i++) {
        size_t m = (size_t)(b*KK + ty*4 + i);
        #pragma unroll
        for (int c = 0; c < 8; c++) {
            int cc = col0 + tx*8 + c;
            float v = acc[i][c] + g_Z[m*512 + cc] + bias[cc];
            g_X2h[m*HH2 + cc] = __float2bfloat16(fmaxf(v, 0.f));
        }
    }
}

// softmax finalize over the two per-colblock partials
__global__ void k_headfin(const float* __restrict__ bc2,
                          float* __restrict__ pred_out)
{
    int m = blockIdx.x*blockDim.x + threadIdx.x;
    if (m >= MM) return;
    float l0 = g_part[0][2*m]     + g_part[1][2*m]     + bc2[0];
    float l1 = g_part[0][2*m + 1] + g_part[1][2*m + 1] + bc2[1];
    float mx = fmaxf(l0, l1);
    float e0 = expf(l0 - mx), e1 = expf(l1 - mx);
    float inv = 1.0f / (e0 + e1);
    pred_out[2*m]     = e0*inv;
    pred_out[2*m + 1] = e1*inv;
}

// ---------------- launch -----------------------------------------------------

extern "C" void kernel_launch(void* const* d_in, const int* in_sizes, int n_in,
                              void* d_out, int out_size)
{
    const int*   indexes  = (const int*)  d_in[0];
    const float* features = (const float*)d_in[1];
    const int*   labels   = (const int*)  d_in[2];
    const int*   knn      = (const int*)  d_in[5];
    const float* all_pred = (const float*)d_in[6];
    const float* W1  = (const float*)d_in[7];
    const float* b1  = (const float*)d_in[8];
    const float* W2  = (const float*)d_in[9];
    const float* b2  = (const float*)d_in[10];
    const float* Wc1 = (const float*)d_in[11];
    const float* bc1 = (const float*)d_in[12];
    const float* pa  = (const float*)d_in[13];
    const float* Wc2 = (const float*)d_in[14];
    const float* bc2 = (const float*)d_in[15];

    float* out = (float*)d_out;
    float* pred_out = out;
    float* simm_out = out + (size_t)MM*2;

    cudaFuncSetAttribute(k_mma_gemm, cudaFuncAttributeMaxDynamicSharedMemorySize,
                         GEMM_SMEM);
    cudaFuncSetAttribute(k_mma_gemm_head, cudaFuncAttributeMaxDynamicSharedMemorySize,
                         GEMM_SMEM);

    __nv_bfloat16 *pA1h,*pW1h,*pW2h,*pWch,*pX1h,*pX2h;
    float *pU,*pZ;
    cudaGetSymbolAddress((void**)&pA1h, g_A1h);
    cudaGetSymbolAddress((void**)&pW1h, g_W1h);
    cudaGetSymbolAddress((void**)&pW2h, g_W2h);
    cudaGetSymbolAddress((void**)&pWch, g_Wch);
    cudaGetSymbolAddress((void**)&pX1h, g_X1h);
    cudaGetSymbolAddress((void**)&pX2h, g_X2h);
    cudaGetSymbolAddress((void**)&pU,  g_U);
    cudaGetSymbolAddress((void**)&pZ,  g_Z);

    // ---- fork S1: weight conversions (off critical path) ----
    cudaEventRecord(g_evF1, 0);
    cudaStreamWaitEvent(g_s1, g_evF1, 0);
    k_convW<<<(1024u*DD)/256, 256, 0, g_s1>>>(W1, NHID, DD, NHID, pW1h);
    k_convW<<<(512u*NHID)/256, 256, 0, g_s1>>>(W2, HH2, NHID, HH2, pW2h);
    k_convW<<<(HH2*HH2)/256, 256, 0, g_s1>>>(Wc1, HH2, HH2, HH2, pWch);
    cudaEventRecord(g_evW, g_s1);

    // ---- legacy: cluster chain (g_icnt zeroed at tail of previous replay) ----
    k_count<<<(NPTS/4 + 255)/256, 256>>>(labels);
    k_scan<<<1, 256>>>();
    k_scatter<<<(NPTS + 255)/256, 256>>>(labels);
    k_cmean<<<CC + BB, 256>>>(features, indexes, simm_out);
    k_rowmap<<<(MM + 255)/256, 256>>>(labels, knn);
    cudaEventRecord(g_evF2, 0);

    // S1 tail: zero g_icnt for next replay (after cmean consumed it)
    cudaStreamWaitEvent(g_s1, g_evF2, 0);
    k_zeroc<<<(CC + 255)/256, 256, 0, g_s1>>>();
    cudaEventRecord(g_evZ, g_s1);

    // ---- fork S2: gram + adjacency (overlaps layer-1 GEMM) ----
    cudaStreamWaitEvent(g_s2, g_evF2, 0);
    k_gram_mma<<<BB, 256, 0, g_s2>>>();
    k_buildA<<<BB*KK, KK, 0, g_s2>>>(all_pred);
    cudaEventRecord(g_evG, g_s2);

    // ---- legacy: layer 1 GEMM (needs cmean + convW) ----
    cudaStreamWaitEvent(0, g_evW, 0);
    k_mma_gemm<<<dim3(1024/128, MU/128), 256, GEMM_SMEM>>>(DD, pA1h, pW1h, pU, 1024);

    // join gram branch, then combine + rest
    cudaStreamWaitEvent(0, g_evG, 0);
    k_combine1<<<dim3(NHID/128, BB), 256>>>(b1);
    k_mma_gemm<<<dim3(512/128, MM/128), 256, GEMM_SMEM>>>(NHID, pX1h, pW2h, pZ, 512);
    k_combine2<<<dim3(HH2/128, BB), 256>>>(b2);
    k_mma_gemm_head<<<dim3(HH2/128, MM/128), 256, GEMM_SMEM>>>(pX2h, pWch, bc1, pa, Wc2);
    cudaStreamWaitEvent(0, g_evZ, 0);
    k_headfin<<<(MM + 255)/256, 256>>>(bc2, pred_out);

    (void)in_sizes; (void)n_in; (void)out_size;
}